// round 2
// baseline (speedup 1.0000x reference)
#include <cuda_runtime.h>
#include <cuda_bf16.h>
#include <math.h>

#define SEQ   128
#define BAT   32
#define EH    512
#define EO    256
#define HID   512
#define G3    1536
#define OUTD  256
#define MROWS (SEQ*BAT)
#define THRESH 1e-6f

typedef unsigned long long ull;

// ---------------- scratch (device globals; no allocation allowed) ----------
__device__ float g_emb[MROWS * EO];          // 4 MB
__device__ float g_xproj[MROWS * G3];        // 25 MB
__device__ float g_h[2][BAT * HID];          // ping-pong hidden state
__device__ unsigned g_bar_count = 0;
__device__ unsigned g_bar_gen   = 0;

// ---------------- f32x2 helpers -------------------------------------------
__device__ __forceinline__ ull pack2(float lo, float hi) {
    ull r; asm("mov.b64 %0, {%1, %2};" : "=l"(r) : "f"(lo), "f"(hi)); return r;
}
__device__ __forceinline__ float2 unpack2(ull v) {
    float2 r; asm("mov.b64 {%0, %1}, %2;" : "=f"(r.x), "=f"(r.y) : "l"(v)); return r;
}
__device__ __forceinline__ void fma2(ull& d, ull a, ull b) {
    asm("fma.rn.f32x2 %0, %1, %2, %3;" : "=l"(d) : "l"(a), "l"(b), "l"(d));
}
__device__ __forceinline__ float thr(float v) { return v > THRESH ? v : 0.0f; }

// ---------------- grid barrier (persistent kernel) ------------------------
__device__ __forceinline__ void grid_barrier(unsigned nCTA) {
    __syncthreads();
    if (threadIdx.x == 0) {
        unsigned gen = atomicAdd(&g_bar_gen, 0u);
        unsigned arrived = atomicAdd(&g_bar_count, 1u);
        if (arrived == nCTA - 1) {
            atomicExch(&g_bar_count, 0u);
            __threadfence();
            atomicAdd(&g_bar_gen, 1u);
        } else {
            while (atomicAdd(&g_bar_gen, 0u) == gen) { }
        }
        __threadfence();
    }
    __syncthreads();
}

// ===========================================================================
// GEMM 1 (fused embedding): emb = thr( thr(W1[tok]+b1) @ W2 + b2 )
//   M=4096 K=512 N=256. Tiles 64x64x16, 256 threads, 4x4 micro-tile (f32x2).
// ===========================================================================
__global__ __launch_bounds__(256) void gemm_embed_kernel(
    const int* __restrict__ tok, const float* __restrict__ W1,
    const float* __restrict__ b1, const float* __restrict__ W2,
    const float* __restrict__ b2)
{
    __shared__ __align__(16) float As[16][68];
    __shared__ __align__(16) float Bs[16][68];

    const int bm = blockIdx.x, bn = blockIdx.y;
    const int t  = threadIdx.x;
    const int tx = t & 15, ty = t >> 4;

    const int arow = t >> 2, aseg = t & 3;
    const int trow = tok[bm * 64 + arow];
    const float* w1row = W1 + (size_t)trow * EH;

    const int brow = t >> 4, bseg = t & 15;

    ull acc[4][2] = {};

    for (int kt = 0; kt < EH; kt += 16) {
        float4 a4 = *(const float4*)(w1row + kt + aseg * 4);
        float4 bb = *(const float4*)(b1 + kt + aseg * 4);
        a4.x = thr(a4.x + bb.x); a4.y = thr(a4.y + bb.y);
        a4.z = thr(a4.z + bb.z); a4.w = thr(a4.w + bb.w);
        As[aseg * 4 + 0][arow] = a4.x;
        As[aseg * 4 + 1][arow] = a4.y;
        As[aseg * 4 + 2][arow] = a4.z;
        As[aseg * 4 + 3][arow] = a4.w;
        *(float4*)&Bs[brow][bseg * 4] =
            *(const float4*)(W2 + (size_t)(kt + brow) * EO + bn * 64 + bseg * 4);
        __syncthreads();
        #pragma unroll
        for (int kk = 0; kk < 16; kk++) {
            float4 av = *(const float4*)&As[kk][ty * 4];
            ulonglong2 bv = *(const ulonglong2*)&Bs[kk][tx * 4];
            ull a0 = pack2(av.x, av.x), a1 = pack2(av.y, av.y);
            ull a2 = pack2(av.z, av.z), a3 = pack2(av.w, av.w);
            fma2(acc[0][0], a0, bv.x); fma2(acc[0][1], a0, bv.y);
            fma2(acc[1][0], a1, bv.x); fma2(acc[1][1], a1, bv.y);
            fma2(acc[2][0], a2, bv.x); fma2(acc[2][1], a2, bv.y);
            fma2(acc[3][0], a3, bv.x); fma2(acc[3][1], a3, bv.y);
        }
        __syncthreads();
    }
    const int m0 = bm * 64 + ty * 4, n0 = bn * 64 + tx * 4;
    #pragma unroll
    for (int i = 0; i < 4; i++) {
        #pragma unroll
        for (int p = 0; p < 2; p++) {
            float2 v = unpack2(acc[i][p]);
            int n = n0 + p * 2;
            v.x = thr(v.x + b2[n]);
            v.y = thr(v.y + b2[n + 1]);
            *(float2*)&g_emb[(size_t)(m0 + i) * EO + n] = v;
        }
    }
}

// ===========================================================================
// GEMM 2 (NT): xproj = emb @ W_ih^T + b_ih   M=4096 K=256 N=1536
// ===========================================================================
__global__ __launch_bounds__(256) void gemm_xproj_kernel(
    const float* __restrict__ W_ih, const float* __restrict__ b_ih)
{
    __shared__ __align__(16) float As[16][68];
    __shared__ __align__(16) float Bs[16][68];

    const int bm = blockIdx.x, bn = blockIdx.y;
    const int t  = threadIdx.x;
    const int tx = t & 15, ty = t >> 4;
    const int row = t >> 2, seg = t & 3;

    ull acc[4][2] = {};

    for (int kt = 0; kt < EO; kt += 16) {
        float4 a4 = *(const float4*)(g_emb + (size_t)(bm * 64 + row) * EO + kt + seg * 4);
        As[seg * 4 + 0][row] = a4.x;
        As[seg * 4 + 1][row] = a4.y;
        As[seg * 4 + 2][row] = a4.z;
        As[seg * 4 + 3][row] = a4.w;
        float4 b4 = *(const float4*)(W_ih + (size_t)(bn * 64 + row) * EO + kt + seg * 4);
        Bs[seg * 4 + 0][row] = b4.x;
        Bs[seg * 4 + 1][row] = b4.y;
        Bs[seg * 4 + 2][row] = b4.z;
        Bs[seg * 4 + 3][row] = b4.w;
        __syncthreads();
        #pragma unroll
        for (int kk = 0; kk < 16; kk++) {
            float4 av = *(const float4*)&As[kk][ty * 4];
            ulonglong2 bv = *(const ulonglong2*)&Bs[kk][tx * 4];
            ull a0 = pack2(av.x, av.x), a1 = pack2(av.y, av.y);
            ull a2 = pack2(av.z, av.z), a3 = pack2(av.w, av.w);
            fma2(acc[0][0], a0, bv.x); fma2(acc[0][1], a0, bv.y);
            fma2(acc[1][0], a1, bv.x); fma2(acc[1][1], a1, bv.y);
            fma2(acc[2][0], a2, bv.x); fma2(acc[2][1], a2, bv.y);
            fma2(acc[3][0], a3, bv.x); fma2(acc[3][1], a3, bv.y);
        }
        __syncthreads();
    }
    const int m0 = bm * 64 + ty * 4, n0 = bn * 64 + tx * 4;
    #pragma unroll
    for (int i = 0; i < 4; i++) {
        #pragma unroll
        for (int p = 0; p < 2; p++) {
            float2 v = unpack2(acc[i][p]);
            int n = n0 + p * 2;
            v.x += b_ih[n];
            v.y += b_ih[n + 1];
            *(float2*)&g_xproj[(size_t)(m0 + i) * G3 + n] = v;
        }
    }
}

// ===========================================================================
// GRU recurrence: persistent kernel, 128 CTAs x 128 threads.
// CTA = (bg in 0..3, jg in 0..31): owns b in [bg*8,+8), j in [jg*16,+16).
// W_hh slice (3 gates x 16 rows x 512) in SMEM once; h slice (8x512)
// reloaded per step via .cg; one grid barrier per step (ping-pong h).
// ===========================================================================
#define GRU_NCTA   128
#define GRU_WS     (3 * 128 * 16 * 4)      // floats
#define GRU_HSTR   516
#define GRU_SMEMB  ((GRU_WS + 8 * GRU_HSTR) * 4)

__global__ __launch_bounds__(128, 1) void gru_kernel(
    const float* __restrict__ W_hh, const float* __restrict__ b_hh)
{
    extern __shared__ __align__(16) float smem[];
    float* w_s = smem;                 // [gate][kq][j][4]
    float* h_s = smem + GRU_WS;        // [8][516]

    const int t  = threadIdx.x;
    const int jg = blockIdx.x & 31;
    const int bg = blockIdx.x >> 5;

    // stage W_hh slice (once for all 128 steps)
    for (int idx = t; idx < 3 * 16 * 128; idx += 128) {
        int kq = idx & 127;
        int jj = (idx >> 7) & 15;
        int g  = idx >> 11;
        float4 v = *(const float4*)(W_hh + ((size_t)(g * HID + jg * 16 + jj)) * HID + kq * 4);
        *(float4*)(w_s + ((g * 128 + kq) * 16 + jj) * 4) = v;
    }
    // zero-init our slice of h buffer 0
    {
        int bl = t >> 4, jj = t & 15;
        g_h[0][(bg * 8 + bl) * HID + jg * 16 + jj] = 0.0f;
    }
    __syncthreads();
    __threadfence();
    grid_barrier(GRU_NCTA);

    const int j     = (t & 3) + ((t >> 5) << 2);
    const int bl    = (t >> 2) & 7;
    const int b     = bg * 8 + bl;
    const int jglob = jg * 16 + j;

    const float bhr = b_hh[jglob];
    const float bhz = b_hh[HID + jglob];
    const float bhn = b_hh[2 * HID + jglob];

    const float* hsrow = h_s + bl * GRU_HSTR;
    const float* wr_p  = w_s + j * 4;
    const float* wz_p  = w_s + 128 * 64 + j * 4;
    const float* wn_p  = w_s + 2 * 128 * 64 + j * 4;

    for (int step = 0; step < SEQ; step++) {
        const float* cur = g_h[step & 1];
        float* nxt = g_h[(step & 1) ^ 1];

        for (int r = t; r < 8 * 128; r += 128) {
            int rb = r >> 7, rk = r & 127;
            float4 v = __ldcg((const float4*)(cur + (size_t)(bg * 8 + rb) * HID + rk * 4));
            *(float4*)(h_s + rb * GRU_HSTR + rk * 4) = v;
        }
        __syncthreads();

        ull ar0 = 0, ar1 = 0, az0 = 0, az1 = 0, an0 = 0, an1 = 0;
        #pragma unroll 4
        for (int kq = 0; kq < 128; kq++) {
            ulonglong2 hv = *(const ulonglong2*)(hsrow + kq * 4);
            ulonglong2 wr = *(const ulonglong2*)(wr_p + kq * 64);
            ulonglong2 wz = *(const ulonglong2*)(wz_p + kq * 64);
            ulonglong2 wn = *(const ulonglong2*)(wn_p + kq * 64);
            fma2(ar0, hv.x, wr.x); fma2(ar1, hv.y, wr.y);
            fma2(az0, hv.x, wz.x); fma2(az1, hv.y, wz.y);
            fma2(an0, hv.x, wn.x); fma2(an1, hv.y, wn.y);
        }
        float2 fr0 = unpack2(ar0), fr1 = unpack2(ar1);
        float2 fz0 = unpack2(az0), fz1 = unpack2(az1);
        float2 fn0 = unpack2(an0), fn1 = unpack2(an1);
        float ghr = (fr0.x + fr0.y) + (fr1.x + fr1.y) + bhr;
        float ghz = (fz0.x + fz0.y) + (fz1.x + fz1.y) + bhz;
        float ghn = (fn0.x + fn0.y) + (fn1.x + fn1.y) + bhn;

        size_t xb = ((size_t)(step * BAT + b)) * G3 + jglob;
        float xr = __ldcg(g_xproj + xb);
        float xz = __ldcg(g_xproj + xb + HID);
        float xn = __ldcg(g_xproj + xb + 2 * HID);

        float r = 1.0f / (1.0f + expf(-(xr + ghr)));
        float z = 1.0f / (1.0f + expf(-(xz + ghz)));
        float n = tanhf(xn + r * ghn);
        float hprev = hsrow[jglob];
        float hnew  = (1.0f - z) * n + z * hprev;

        nxt[(size_t)b * HID + jglob] = hnew;
        __threadfence();
        grid_barrier(GRU_NCTA);
    }
    // SEQ even -> final hidden in g_h[0]
}

// ===========================================================================
// Head: out[b][o] = hT[b] . W3[:,o] + b3[o]
// ===========================================================================
__global__ __launch_bounds__(256) void head_kernel(
    const float* __restrict__ W3, const float* __restrict__ b3,
    float* __restrict__ out)
{
    __shared__ __align__(16) float h_s[HID];
    const int b = blockIdx.x, t = threadIdx.x;
    for (int k = t; k < HID; k += 256) h_s[k] = g_h[0][b * HID + k];
    __syncthreads();
    float acc = b3[t];
    #pragma unroll 8
    for (int kk = 0; kk < HID; kk++)
        acc = fmaf(h_s[kk], W3[(size_t)kk * OUTD + t], acc);
    out[b * OUTD + t] = acc;
}

// ===========================================================================
extern "C" void kernel_launch(void* const* d_in, const int* in_sizes, int n_in,
                              void* d_out, int out_size)
{
    const int*   input = (const int*)  d_in[0];
    const float* W1    = (const float*)d_in[1];
    const float* b1    = (const float*)d_in[2];
    const float* W2    = (const float*)d_in[3];
    const float* b2    = (const float*)d_in[4];
    const float* W_ih  = (const float*)d_in[5];
    const float* W_hh  = (const float*)d_in[6];
    const float* b_ih  = (const float*)d_in[7];
    const float* b_hh  = (const float*)d_in[8];
    const float* W3    = (const float*)d_in[9];
    const float* b3    = (const float*)d_in[10];
    float* out = (float*)d_out;

    static int configured = 0;
    if (!configured) {
        cudaFuncSetAttribute(gru_kernel,
            cudaFuncAttributeMaxDynamicSharedMemorySize, GRU_SMEMB);
        configured = 1;
    }

    dim3 g1(MROWS / 64, EO / 64);
    gemm_embed_kernel<<<g1, 256>>>(input, W1, b1, W2, b2);

    dim3 g2(MROWS / 64, G3 / 64);
    gemm_xproj_kernel<<<g2, 256>>>(W_ih, b_ih);

    gru_kernel<<<GRU_NCTA, 128, GRU_SMEMB>>>(W_hh, b_hh);

    head_kernel<<<BAT, OUTD>>>(W3, b3, out);
}